// round 5
// baseline (speedup 1.0000x reference)
#include <cuda_runtime.h>
#include <math.h>

// Shape fixed by reference: x,y = [16, 3, 512, 512] f32
#define BATCH   16
#define HDIM    512
#define WDIM    512
#define RSTRIP  32                    // output rows per block
#define STRIPS  (HDIM / RSTRIP)       // 16
#define NBLOCKS (BATCH * STRIPS)      // 256
#define ROWSIN  (RSTRIP + 6)          // 38 input rows incl. halo
#define RGROUPS 4                     // row-groups per block
#define THREADS (RGROUPS * 128)       // 512
#define CHUNKS  ((ROWSIN + RGROUPS - 1) / RGROUPS)  // 10
#define EPSV    1e-6f

__device__ float        g_partials[NBLOCKS];
__device__ unsigned int g_count;     // zero-init at load; reset by last block

__device__ __forceinline__ void rg_barrier(int rg) {
    // 128-thread named barrier per row-group (ids 1..RGROUPS)
    asm volatile("bar.sync %0, %1;" :: "r"(rg + 1), "r"(128) : "memory");
}

__global__ __launch_bounds__(THREADS, 2) void charb_kernel(
    const float* __restrict__ x, const float* __restrict__ y,
    float* __restrict__ out)
{
    __shared__ float drow[RGROUPS][520]; // per-row-group diff row, halo-padded
    __shared__ float hs[16][WDIM];       // ring of horizontal 7-tap sums
    __shared__ float warpsum[THREADS / 32];
    __shared__ bool  isLast;

    const int tid  = threadIdx.x;
    const int rg   = tid >> 7;         // row-group 0..3
    const int c4   = tid & 127;        // float4 column index
    const int col0 = c4 << 2;

    const int blk = blockIdx.x;
    const int b   = blk / STRIPS;
    const int s   = blk % STRIPS;
    const int h0  = s * RSTRIP;

    if (c4 == 0) {                     // zero side halos once
        drow[rg][0] = drow[rg][1] = drow[rg][2] = drow[rg][3] = 0.f;
        drow[rg][516] = drow[rg][517] = drow[rg][518] = drow[rg][519] = 0.f;
    }

    const size_t plane = (size_t)HDIM * WDIM;
    const float* xb = x + (size_t)b * 3 * plane;
    const float* yb = y + (size_t)b * 3 * plane;

    float4 a0, a1, a2, q0, q1, q2;     // pipelined raw loads (cur chunk)
    bool   valid;

    {   // prologue: load chunk 0 (input row idx = rg)
        const int r = h0 - 3 + rg;
        valid = (r >= 0) && (r < HDIM);
        if (valid) {
            const float* xp = xb + (size_t)r * WDIM + col0;
            const float* yp = yb + (size_t)r * WDIM + col0;
            a0 = *(const float4*)(xp);
            a1 = *(const float4*)(xp + plane);
            a2 = *(const float4*)(xp + 2 * plane);
            q0 = *(const float4*)(yp);
            q1 = *(const float4*)(yp + plane);
            q2 = *(const float4*)(yp + 2 * plane);
        }
    }

    float acc = 0.f;

    #pragma unroll 1
    for (int ch = 0; ch < CHUNKS; ++ch) {
        const int idx = ch * RGROUPS + rg;  // input-row index within strip stream

        // channel-summed diff for current chunk -> smem
        float4 d = make_float4(0.f, 0.f, 0.f, 0.f);
        if (valid) {
            d.x = (a0.x - q0.x) + (a1.x - q1.x) + (a2.x - q2.x);
            d.y = (a0.y - q0.y) + (a1.y - q1.y) + (a2.y - q2.y);
            d.z = (a0.z - q0.z) + (a1.z - q1.z) + (a2.z - q2.z);
            d.w = (a0.w - q0.w) + (a1.w - q1.w) + (a2.w - q2.w);
        }
        *(float4*)&drow[rg][4 + col0] = d;

        // prefetch next chunk (latency hidden behind both smem phases)
        const int nidx = idx + RGROUPS;
        const int nr   = h0 - 3 + nidx;
        valid = (nidx < ROWSIN) && (nr >= 0) && (nr < HDIM);
        if (valid) {
            const float* xp = xb + (size_t)nr * WDIM + col0;
            const float* yp = yb + (size_t)nr * WDIM + col0;
            a0 = *(const float4*)(xp);
            a1 = *(const float4*)(xp + plane);
            a2 = *(const float4*)(xp + 2 * plane);
            q0 = *(const float4*)(yp);
            q1 = *(const float4*)(yp + plane);
            q2 = *(const float4*)(yp + 2 * plane);
        }

        rg_barrier(rg);                 // drow ready within this row-group

        // horizontal 7-tap sums for 4 columns via 3 aligned LDS.128
        float f[12];
        *(float4*)&f[0] = *(const float4*)&drow[rg][col0];
        *(float4*)&f[4] = *(const float4*)&drow[rg][col0 + 4];
        *(float4*)&f[8] = *(const float4*)&drow[rg][col0 + 8];
        const float s0 = ((f[1] + f[2]) + (f[3] + f[4])) + ((f[5] + f[6]) + f[7]);
        const float s1 = s0 - f[1] + f[8];
        const float s2 = s1 - f[2] + f[9];
        const float s3 = s2 - f[3] + f[10];
        *(float4*)&hs[idx & 15][col0] = make_float4(s0, s1, s2, s3);

        __syncthreads();                // hs rows from all row-groups visible
                                        // (ring WAR safe: next-chunk writes land
                                        //  10..13 slots away mod 16 from reads)

        // vertical 7-tap + Charbonnier for output row o = idx - 6
        const int o = idx - 6;
        if (o >= 0 && o < RSTRIP) {
            float4 v = *(const float4*)&hs[o & 15][col0];
            #pragma unroll
            for (int t = 1; t < 7; ++t) {
                const float4 hv = *(const float4*)&hs[(o + t) & 15][col0];
                v.x += hv.x; v.y += hv.y; v.z += hv.z; v.w += hv.w;
            }
            const float inv = 1.f / 49.f;
            v.x *= inv; v.y *= inv; v.z *= inv; v.w *= inv;
            acc += (sqrtf(v.x * v.x + EPSV) + sqrtf(v.y * v.y + EPSV))
                 + (sqrtf(v.z * v.z + EPSV) + sqrtf(v.w * v.w + EPSV));
        }
    }

    // block reduction
    #pragma unroll
    for (int off = 16; off; off >>= 1) acc += __shfl_xor_sync(0xffffffffu, acc, off);
    if ((tid & 31) == 0) warpsum[tid >> 5] = acc;
    __syncthreads();
    if (tid < 32) {
        float v = (tid < THREADS / 32) ? warpsum[tid] : 0.f;
        #pragma unroll
        for (int off = 8; off; off >>= 1) v += __shfl_xor_sync(0xffffffffu, v, off);
        if (tid == 0) {
            g_partials[blk] = v;
            __threadfence();
            const unsigned int t = atomicAdd(&g_count, 1u);
            isLast = (t == NBLOCKS - 1);
        }
    }
    __syncthreads();

    // last-arriving block folds the 256 partials -> scalar (deterministic order)
    if (isLast) {
        __threadfence();
        float v = (tid < NBLOCKS) ? g_partials[tid] : 0.f;
        #pragma unroll
        for (int off = 16; off; off >>= 1) v += __shfl_xor_sync(0xffffffffu, v, off);
        if ((tid & 31) == 0) warpsum[tid >> 5] = v;
        __syncthreads();
        if (tid < 32) {
            float v2 = (tid < THREADS / 32) ? warpsum[tid] : 0.f;
            #pragma unroll
            for (int off = 8; off; off >>= 1) v2 += __shfl_xor_sync(0xffffffffu, v2, off);
            if (tid == 0) {
                out[0]  = v2 / (float)((size_t)BATCH * HDIM * WDIM);
                g_count = 0u;
            }
        }
    }
}

extern "C" void kernel_launch(void* const* d_in, const int* in_sizes, int n_in,
                              void* d_out, int out_size)
{
    (void)in_sizes; (void)n_in; (void)out_size;
    const float* x = (const float*)d_in[0];
    const float* y = (const float*)d_in[1];
    float* out = (float*)d_out;

    charb_kernel<<<NBLOCKS, THREADS>>>(x, y, out);
}